// round 5
// baseline (speedup 1.0000x reference)
#include <cuda_runtime.h>
#include <math.h>

// RippleNet fused, GB300 sm_103a
// H=2, B=2048, M=64, D=16, N_ENT=500000, N_REL=32
#define RN_H 2
#define RN_B 2048
#define RN_M 64
#define RN_D 16
#define RN_NREL 32
#define RN_BPB 8   // batches per block in vprep

// scratch: V[b][r][j] = sum_i item[b][i] * R[r][i][j]   (2048*32*16 floats = 4MB)
__device__ float g_V[RN_B * RN_NREL * RN_D];

// ---------------- Kernel 1: V precompute ----------------
__global__ __launch_bounds__(128)
void vprep_kernel(const int* __restrict__ items,
                  const float* __restrict__ ent,
                  const float* __restrict__ rel)
{
    const int tid = threadIdx.x;
    const int r   = tid >> 2;
    const int j4  = tid & 3;

    float4 Rreg[RN_D];
    #pragma unroll
    for (int i = 0; i < RN_D; i++)
        Rreg[i] = __ldg((const float4*)(rel + (r * RN_D + i) * RN_D) + j4);

    __shared__ float s_it[RN_BPB][RN_D];
    const int b0 = blockIdx.x * RN_BPB;
    {
        const int row = tid >> 4;
        const int col = tid & 15;
        const int it  = items[b0 + row];
        s_it[row][col] = __ldg(ent + (size_t)it * RN_D + col);
    }
    __syncthreads();

    #pragma unroll
    for (int bb = 0; bb < RN_BPB; bb++) {
        float4 acc = make_float4(0.f, 0.f, 0.f, 0.f);
        #pragma unroll
        for (int i = 0; i < RN_D; i++) {
            const float s = s_it[bb][i];
            acc.x = fmaf(s, Rreg[i].x, acc.x);
            acc.y = fmaf(s, Rreg[i].y, acc.y);
            acc.z = fmaf(s, Rreg[i].z, acc.z);
            acc.w = fmaf(s, Rreg[i].w, acc.w);
        }
        *((float4*)(g_V + (size_t)(b0 + bb) * (RN_NREL * RN_D)) + tid) = acc;
    }
}

// ---------------- Kernel 2: main ----------------
__global__ __launch_bounds__(128, 8)
void ripple_main(const int* __restrict__ items,
                 const int* __restrict__ heads,
                 const int* __restrict__ rels,
                 const int* __restrict__ tails,
                 const float* __restrict__ ent,
                 float* __restrict__ out)
{
    const int b    = blockIdx.x;
    const int tid  = threadIdx.x;
    const int lane = tid & 31;
    const int warp = tid >> 5;
    const int h    = tid >> 6;
    const int q    = tid & 3;
    const int gbase = lane & ~3;

    __shared__ float s_item[RN_D];
    __shared__ float s_v[RN_NREL][RN_D];
    __shared__ float s_mx[4];
    __shared__ float s_sm[4];
    __shared__ float s_part[4][RN_D];

    if (tid < RN_D) {
        const int it = items[b];
        s_item[tid] = __ldg(ent + (size_t)it * RN_D + tid);
    }
    ((float4*)s_v)[tid] = __ldg((const float4*)(g_V + (size_t)b * (RN_NREL * RN_D)) + tid);

    const int gidx = (h * RN_B + b) * RN_M + (tid & 63);
    const int hidx_own = heads[gidx];
    const int ridx_own = rels[gidx];
    const int tidx_own = tails[gidx];

    // ---- prefetch tail quarters into L1 NOW (they don't depend on softmax) ----
    #pragma unroll
    for (int k = 0; k < 4; k++) {
        const int tk = __shfl_sync(0xFFFFFFFFu, tidx_own, gbase + k);
        const float4* ta = (const float4*)(ent + (size_t)tk * RN_D) + q;
        asm volatile("prefetch.global.L1 [%0];" :: "l"(ta));
    }

    __syncthreads();

    // ---- phase A: logits (cooperative quarter-row gathers) ----
    float part[4];
    #pragma unroll
    for (int k = 0; k < 4; k++) {
        const int src = gbase + k;
        const int hk  = __shfl_sync(0xFFFFFFFFu, hidx_own, src);
        const int rk  = __shfl_sync(0xFFFFFFFFu, ridx_own, src);
        const float4 hv = __ldg((const float4*)(ent + (size_t)hk * RN_D) + q);
        const float4 vv = *((const float4*)&s_v[rk][0] + q);
        part[k] = hv.x * vv.x + hv.y * vv.y + hv.z * vv.z + hv.w * vv.w;
    }
    #pragma unroll
    for (int k = 0; k < 4; k++) {
        part[k] += __shfl_xor_sync(0xFFFFFFFFu, part[k], 1);
        part[k] += __shfl_xor_sync(0xFFFFFFFFu, part[k], 2);
    }
    float logit = part[0];
    if (q == 1) logit = part[1];
    else if (q == 2) logit = part[2];
    else if (q == 3) logit = part[3];

    // ---- phase B: softmax over m (64 values = 2 warps per h) ----
    float mx = logit;
    #pragma unroll
    for (int o = 16; o; o >>= 1)
        mx = fmaxf(mx, __shfl_xor_sync(0xFFFFFFFFu, mx, o));
    if (lane == 0) s_mx[warp] = mx;
    __syncthreads();
    mx = fmaxf(s_mx[h * 2], s_mx[h * 2 + 1]);

    const float p = __expf(logit - mx);
    float sm = p;
    #pragma unroll
    for (int o = 16; o; o >>= 1)
        sm += __shfl_xor_sync(0xFFFFFFFFu, sm, o);
    if (lane == 0) s_sm[warp] = sm;
    __syncthreads();
    sm = s_sm[h * 2] + s_sm[h * 2 + 1];
    const float pi = p / sm;

    // ---- phase C: weighted tails (loads should hit prefetched L1 lines) ----
    float4 acc = make_float4(0.f, 0.f, 0.f, 0.f);
    #pragma unroll
    for (int k = 0; k < 4; k++) {
        const int src = gbase + k;
        const int tk  = __shfl_sync(0xFFFFFFFFu, tidx_own, src);
        const float pk = __shfl_sync(0xFFFFFFFFu, pi, src);
        const float4 tv = __ldg((const float4*)(ent + (size_t)tk * RN_D) + q);
        acc.x = fmaf(pk, tv.x, acc.x);
        acc.y = fmaf(pk, tv.y, acc.y);
        acc.z = fmaf(pk, tv.z, acc.z);
        acc.w = fmaf(pk, tv.w, acc.w);
    }
    #pragma unroll
    for (int o = 4; o <= 16; o <<= 1) {
        acc.x += __shfl_xor_sync(0xFFFFFFFFu, acc.x, o);
        acc.y += __shfl_xor_sync(0xFFFFFFFFu, acc.y, o);
        acc.z += __shfl_xor_sync(0xFFFFFFFFu, acc.z, o);
        acc.w += __shfl_xor_sync(0xFFFFFFFFu, acc.w, o);
    }
    if (lane < 4)
        *((float4*)&s_part[warp][0] + lane) = acc;
    __syncthreads();

    // ---- final dot + sigmoid ----
    if (tid < RN_D) {
        const float u = s_part[0][tid] + s_part[1][tid]
                      + s_part[2][tid] + s_part[3][tid];
        float v = u * s_item[tid];
        v += __shfl_xor_sync(0x0000FFFFu, v, 1);
        v += __shfl_xor_sync(0x0000FFFFu, v, 2);
        v += __shfl_xor_sync(0x0000FFFFu, v, 4);
        v += __shfl_xor_sync(0x0000FFFFu, v, 8);
        if (tid == 0)
            out[b] = 1.f / (1.f + __expf(-v));
    }
}

extern "C" void kernel_launch(void* const* d_in, const int* in_sizes, int n_in,
                              void* d_out, int out_size)
{
    const int*   items = (const int*)  d_in[0];
    const int*   heads = (const int*)  d_in[1];
    const int*   rels  = (const int*)  d_in[2];
    const int*   tails = (const int*)  d_in[3];
    const float* ent   = (const float*)d_in[4];
    const float* rel   = (const float*)d_in[5];
    float*       out   = (float*)      d_out;

    vprep_kernel<<<RN_B / RN_BPB, 128>>>(items, ent, rel);
    ripple_main<<<RN_B, 128>>>(items, heads, rels, tails, ent, out);
}